// round 2
// baseline (speedup 1.0000x reference)
#include <cuda_runtime.h>
#include <cuda_bf16.h>
#include <math.h>

// ---------------------------------------------------------------------------
// NeuronBloomBlock: B=2, S=2048, D=2048, H=16, HD=128, FF=8192, fp32.
//   h   = LN(x, ln1)                          [4096, 2048]
//   qkv = h @ wqkv + bqkv                     [4096, 6144]
//   attn = ALiBi-causal-attention(qkv)        [4096, 2048]
//   x1  = x + attn @ wo + bo                  [4096, 2048]
//   h2  = LN(x1, ln2)                         [4096, 2048]
//   ff  = gelu(h2 @ w1 + b1)                  [4096, 8192]
//   out = x1 + ff @ w2 + b2                   [4096, 2048]
// ---------------------------------------------------------------------------

#define NTOK   4096
#define DMODEL 2048
#define DQKV   6144
#define DFF    8192
#define SEQ    2048
#define NHEAD  16
#define HEADD  128
#define LNEPS  1e-5f

// Scratch: h(8.4M) qkv(25.2M) attn(8.4M) x1(8.4M) ff(33.6M) floats
#define OFF_H    ((size_t)0)
#define OFF_QKV  ((size_t)8388608)
#define OFF_ATTN ((size_t)(8388608 + 25165824))
#define OFF_X1   ((size_t)(8388608 + 25165824 + 8388608))
#define OFF_FF   ((size_t)(8388608 + 25165824 + 8388608 + 8388608))
#define SCRATCH_FLOATS ((size_t)(8388608 + 25165824 + 8388608 + 8388608 + 33554432))

__device__ float g_scratch[SCRATCH_FLOATS];

// ---------------------------------------------------------------------------
// LayerNorm: one block per row (D=2048), 256 threads, 8 elems/thread.
// ---------------------------------------------------------------------------
__global__ void ln_kernel(const float* __restrict__ x, const float* __restrict__ w,
                          const float* __restrict__ bb, float* __restrict__ out) {
    __shared__ float red[8];
    __shared__ float stat[2];
    int row = blockIdx.x;
    int tid = threadIdx.x;
    const float* xr = x + (size_t)row * DMODEL;

    float4 a = *(const float4*)(xr + tid * 4);
    float4 b = *(const float4*)(xr + 1024 + tid * 4);

    float s = a.x + a.y + a.z + a.w + b.x + b.y + b.z + b.w;
    #pragma unroll
    for (int o = 16; o; o >>= 1) s += __shfl_xor_sync(0xffffffffu, s, o);
    if ((tid & 31) == 0) red[tid >> 5] = s;
    __syncthreads();
    if (tid < 8) {
        float t = red[tid];
        #pragma unroll
        for (int o = 4; o; o >>= 1) t += __shfl_xor_sync(0xffu, t, o);
        if (tid == 0) stat[0] = t;
    }
    __syncthreads();
    float mean = stat[0] * (1.0f / (float)DMODEL);

    float dx0 = a.x - mean, dx1 = a.y - mean, dx2 = a.z - mean, dx3 = a.w - mean;
    float dy0 = b.x - mean, dy1 = b.y - mean, dy2 = b.z - mean, dy3 = b.w - mean;
    float s2 = dx0*dx0 + dx1*dx1 + dx2*dx2 + dx3*dx3
             + dy0*dy0 + dy1*dy1 + dy2*dy2 + dy3*dy3;
    __syncthreads();   // protect red[] reuse
    #pragma unroll
    for (int o = 16; o; o >>= 1) s2 += __shfl_xor_sync(0xffffffffu, s2, o);
    if ((tid & 31) == 0) red[tid >> 5] = s2;
    __syncthreads();
    if (tid < 8) {
        float t = red[tid];
        #pragma unroll
        for (int o = 4; o; o >>= 1) t += __shfl_xor_sync(0xffu, t, o);
        if (tid == 0) stat[1] = t;
    }
    __syncthreads();
    float inv = rsqrtf(stat[1] * (1.0f / (float)DMODEL) + LNEPS);

    float4 w0 = *(const float4*)(w + tid * 4);
    float4 w1 = *(const float4*)(w + 1024 + tid * 4);
    float4 g0 = *(const float4*)(bb + tid * 4);
    float4 g1 = *(const float4*)(bb + 1024 + tid * 4);

    float* orow = out + (size_t)row * DMODEL;
    float4 r0, r1;
    r0.x = dx0 * inv * w0.x + g0.x; r0.y = dx1 * inv * w0.y + g0.y;
    r0.z = dx2 * inv * w0.z + g0.z; r0.w = dx3 * inv * w0.w + g0.w;
    r1.x = dy0 * inv * w1.x + g1.x; r1.y = dy1 * inv * w1.y + g1.y;
    r1.z = dy2 * inv * w1.z + g1.z; r1.w = dy3 * inv * w1.w + g1.w;
    *(float4*)(orow + tid * 4) = r0;
    *(float4*)(orow + 1024 + tid * 4) = r1;
}

// ---------------------------------------------------------------------------
// SGEMM: C[M,N] = A[M,K] @ W[K,N] + bias (+ residual | gelu)
// 128x128x16 tiles, 256 threads, 8x8 per thread (split 4+4 frags).
// ---------------------------------------------------------------------------
#define EPI_BIAS      0
#define EPI_BIAS_RES  1
#define EPI_BIAS_GELU 2

__device__ __forceinline__ float gelu_tanh(float v) {
    float t = tanhf(0.7978845608028654f * (v + 0.044715f * v * v * v));
    return 0.5f * v * (1.0f + t);
}

template<int EPI>
__global__ __launch_bounds__(256, 2)
void sgemm_kernel(const float* __restrict__ A, const float* __restrict__ W,
                  const float* __restrict__ bias, const float* __restrict__ res,
                  float* __restrict__ C, int M, int N, int K) {
    __shared__ float As[16][132];
    __shared__ float Bs[16][128];

    int tid  = threadIdx.x;
    int tcol = tid & 15;
    int trow = tid >> 4;
    int bm = blockIdx.y * 128;
    int bn = blockIdx.x * 128;

    const float* Aptr = A + (size_t)bm * K;
    const float* Wptr = W + bn;

    float acc[8][8];
    #pragma unroll
    for (int i = 0; i < 8; ++i)
        #pragma unroll
        for (int j = 0; j < 8; ++j) acc[i][j] = 0.0f;

    int nk = K >> 4;
    for (int kt = 0; kt < nk; ++kt) {
        #pragma unroll
        for (int u = 0; u < 2; ++u) {
            int idx = tid + u * 256;       // 0..511
            // A tile: 128 rows x 16 k   (store transposed into As[k][m])
            int r  = idx >> 2;
            int k4 = (idx & 3) << 2;
            float4 av = *(const float4*)(Aptr + (size_t)r * K + (kt << 4) + k4);
            As[k4 + 0][r] = av.x;
            As[k4 + 1][r] = av.y;
            As[k4 + 2][r] = av.z;
            As[k4 + 3][r] = av.w;
            // W tile: 16 k x 128 cols
            int r2 = idx >> 5;
            int c4 = (idx & 31) << 2;
            *(float4*)&Bs[r2][c4] =
                *(const float4*)(Wptr + (size_t)((kt << 4) + r2) * N + c4);
        }
        __syncthreads();

        #pragma unroll
        for (int kk = 0; kk < 16; ++kk) {
            float af[8], bf[8];
            *(float4*)&af[0] = *(const float4*)&As[kk][trow * 4];
            *(float4*)&af[4] = *(const float4*)&As[kk][64 + trow * 4];
            *(float4*)&bf[0] = *(const float4*)&Bs[kk][tcol * 4];
            *(float4*)&bf[4] = *(const float4*)&Bs[kk][64 + tcol * 4];
            #pragma unroll
            for (int i = 0; i < 8; ++i)
                #pragma unroll
                for (int j = 0; j < 8; ++j)
                    acc[i][j] = fmaf(af[i], bf[j], acc[i][j]);
        }
        __syncthreads();
    }

    #pragma unroll
    for (int i = 0; i < 8; ++i) {
        int r = bm + ((i < 4) ? (trow * 4 + i) : (64 + trow * 4 + (i - 4)));
        #pragma unroll
        for (int jh = 0; jh < 2; ++jh) {
            int c = bn + tcol * 4 + jh * 64;
            float4 v;
            v.x = acc[i][jh * 4 + 0];
            v.y = acc[i][jh * 4 + 1];
            v.z = acc[i][jh * 4 + 2];
            v.w = acc[i][jh * 4 + 3];
            float4 bv = *(const float4*)(bias + c);
            v.x += bv.x; v.y += bv.y; v.z += bv.z; v.w += bv.w;
            if (EPI == EPI_BIAS_RES) {
                float4 rv = *(const float4*)(res + (size_t)r * N + c);
                v.x += rv.x; v.y += rv.y; v.z += rv.z; v.w += rv.w;
            }
            if (EPI == EPI_BIAS_GELU) {
                v.x = gelu_tanh(v.x); v.y = gelu_tanh(v.y);
                v.z = gelu_tanh(v.z); v.w = gelu_tanh(v.w);
            }
            *(float4*)(C + (size_t)r * N + c) = v;
        }
    }
}

// ---------------------------------------------------------------------------
// Flash attention (fp32) with ALiBi + causal mask.
// grid (S/64, H, B), 256 threads. Q tile 64 rows, K tile 64 keys, HD=128.
// Thread map: tx = tid&15, ty = tid>>4.
//   S stage: rows ty*4+i (i<4), cols j*16+tx (j<4)
//   O stage: rows ty*4+i, cols tx*4+{0..3} and 64+tx*4+{0..3}
// ---------------------------------------------------------------------------
#define AT_SMEM ((3 * 64 * 132 + 64 * 68) * 4)

__global__ __launch_bounds__(256)
void attn_kernel(const float* __restrict__ qkv, float* __restrict__ out) {
    extern __shared__ float sm[];
    float* Qs = sm;                  // [64][132]
    float* Ks = sm + 64 * 132;       // [64][132]
    float* Vs = sm + 2 * 64 * 132;   // [64][132]
    float* Ps = sm + 3 * 64 * 132;   // [64][68]

    int tid = threadIdx.x;
    int tx = tid & 15, ty = tid >> 4;
    int qt = blockIdx.x, h = blockIdx.y, b = blockIdx.z;
    int q0 = qt * 64;

    const float scale = 0.08838834764831845f;   // 1/sqrt(128)
    float slope = exp2f(-0.5f * (float)(h + 1));

    const float* qbase = qkv + (size_t)b * SEQ * DQKV + (size_t)h * HEADD;
    const float* kbase = qbase + DMODEL;
    const float* vbase = qbase + 2 * DMODEL;

    // load Q tile (scaled)
    for (int i = tid; i < 64 * 32; i += 256) {
        int r = i >> 5, c4 = (i & 31) << 2;
        float4 v = *(const float4*)(qbase + (size_t)(q0 + r) * DQKV + c4);
        Qs[r * 132 + c4 + 0] = v.x * scale;
        Qs[r * 132 + c4 + 1] = v.y * scale;
        Qs[r * 132 + c4 + 2] = v.z * scale;
        Qs[r * 132 + c4 + 3] = v.w * scale;
    }

    float m_i[4], l_i[4], acc[4][8];
    #pragma unroll
    for (int i = 0; i < 4; ++i) {
        m_i[i] = -INFINITY; l_i[i] = 0.0f;
        #pragma unroll
        for (int c = 0; c < 8; ++c) acc[i][c] = 0.0f;
    }

    int nkb = qt + 1;
    for (int kb = 0; kb < nkb; ++kb) {
        __syncthreads();   // prev-iter smem reads done
        for (int i = tid; i < 64 * 32; i += 256) {
            int r = i >> 5, c4 = (i & 31) << 2;
            *(float4*)&Ks[r * 132 + c4] =
                *(const float4*)(kbase + (size_t)(kb * 64 + r) * DQKV + c4);
            *(float4*)&Vs[r * 132 + c4] =
                *(const float4*)(vbase + (size_t)(kb * 64 + r) * DQKV + c4);
        }
        __syncthreads();

        // ---- S = Q @ K^T ----
        float s[4][4];
        #pragma unroll
        for (int i = 0; i < 4; ++i)
            #pragma unroll
            for (int j = 0; j < 4; ++j) s[i][j] = 0.0f;

        for (int d4 = 0; d4 < 32; ++d4) {
            float4 qv[4], kv[4];
            #pragma unroll
            for (int i = 0; i < 4; ++i)
                qv[i] = *(const float4*)&Qs[(ty * 4 + i) * 132 + d4 * 4];
            #pragma unroll
            for (int j = 0; j < 4; ++j)
                kv[j] = *(const float4*)&Ks[(j * 16 + tx) * 132 + d4 * 4];
            #pragma unroll
            for (int i = 0; i < 4; ++i)
                #pragma unroll
                for (int j = 0; j < 4; ++j) {
                    s[i][j] = fmaf(qv[i].x, kv[j].x, s[i][j]);
                    s[i][j] = fmaf(qv[i].y, kv[j].y, s[i][j]);
                    s[i][j] = fmaf(qv[i].z, kv[j].z, s[i][j]);
                    s[i][j] = fmaf(qv[i].w, kv[j].w, s[i][j]);
                }
        }

        // ---- ALiBi + mask + online softmax ----
        bool diag = (kb == qt);
        float a4[4];
        #pragma unroll
        for (int i = 0; i < 4; ++i) {
            int gr = q0 + ty * 4 + i;
            float rowmax = -1e30f;
            #pragma unroll
            for (int j = 0; j < 4; ++j) {
                int gc = kb * 64 + j * 16 + tx;
                float val = s[i][j] + slope * (float)(gc - gr);
                if (diag && gc > gr) val = -1e30f;
                s[i][j] = val;
                rowmax = fmaxf(rowmax, val);
            }
            #pragma unroll
            for (int o = 8; o; o >>= 1)
                rowmax = fmaxf(rowmax, __shfl_xor_sync(0xffffffffu, rowmax, o, 16));
            float mnew = fmaxf(m_i[i], rowmax);
            float alpha = expf(m_i[i] - mnew);
            float rowsum = 0.0f;
            #pragma unroll
            for (int j = 0; j < 4; ++j) {
                float p = expf(s[i][j] - mnew);
                s[i][j] = p;
                rowsum += p;
            }
            #pragma unroll
            for (int o = 8; o; o >>= 1)
                rowsum += __shfl_xor_sync(0xffffffffu, rowsum, o, 16);
            l_i[i] = l_i[i] * alpha + rowsum;
            m_i[i] = mnew;
            a4[i] = alpha;
        }

        // stage P to smem
        #pragma unroll
        for (int i = 0; i < 4; ++i)
            #pragma unroll
            for (int j = 0; j < 4; ++j)
                Ps[(ty * 4 + i) * 68 + j * 16 + tx] = s[i][j];
        __syncthreads();

        // ---- O = O*alpha + P @ V ----
        #pragma unroll
        for (int i = 0; i < 4; ++i)
            #pragma unroll
            for (int c = 0; c < 8; ++c) acc[i][c] *= a4[i];

        #pragma unroll 4
        for (int k = 0; k < 64; ++k) {
            float4 v0 = *(const float4*)&Vs[k * 132 + tx * 4];
            float4 v1 = *(const float4*)&Vs[k * 132 + 64 + tx * 4];
            #pragma unroll
            for (int i = 0; i < 4; ++i) {
                float p = Ps[(ty * 4 + i) * 68 + k];
                acc[i][0] = fmaf(p, v0.x, acc[i][0]);
                acc[i][1] = fmaf(p, v0.y, acc[i][1]);
                acc[i][2] = fmaf(p, v0.z, acc[i][2]);
                acc[i][3] = fmaf(p, v0.w, acc[i][3]);
                acc[i][4] = fmaf(p, v1.x, acc[i][4]);
                acc[i][5] = fmaf(p, v1.y, acc[i][5]);
                acc[i][6] = fmaf(p, v1.z, acc[i][6]);
                acc[i][7] = fmaf(p, v1.w, acc[i][7]);
            }
        }
    }

    // write: out[b, q, h*128 + c]
    #pragma unroll
    for (int i = 0; i < 4; ++i) {
        float inv = 1.0f / l_i[i];
        size_t orow = ((size_t)(b * SEQ + q0 + ty * 4 + i)) * DMODEL + h * HEADD;
        float4 o0, o1;
        o0.x = acc[i][0] * inv; o0.y = acc[i][1] * inv;
        o0.z = acc[i][2] * inv; o0.w = acc[i][3] * inv;
        o1.x = acc[i][4] * inv; o1.y = acc[i][5] * inv;
        o1.z = acc[i][6] * inv; o1.w = acc[i][7] * inv;
        *(float4*)(out + orow + tx * 4) = o0;
        *(float4*)(out + orow + 64 + tx * 4) = o1;
    }
}

// ---------------------------------------------------------------------------
extern "C" void kernel_launch(void* const* d_in, const int* in_sizes, int n_in,
                              void* d_out, int out_size) {
    const float* x     = (const float*)d_in[0];
    const float* ln1_w = (const float*)d_in[1];
    const float* ln1_b = (const float*)d_in[2];
    const float* wqkv  = (const float*)d_in[3];
    const float* bqkv  = (const float*)d_in[4];
    const float* wo    = (const float*)d_in[5];
    const float* bo    = (const float*)d_in[6];
    const float* ln2_w = (const float*)d_in[7];
    const float* ln2_b = (const float*)d_in[8];
    const float* w1    = (const float*)d_in[9];
    const float* b1    = (const float*)d_in[10];
    const float* w2    = (const float*)d_in[11];
    const float* b2    = (const float*)d_in[12];
    float* out = (float*)d_out;

    float* base = nullptr;
    cudaGetSymbolAddress((void**)&base, g_scratch);
    float* h    = base + OFF_H;
    float* qkv  = base + OFF_QKV;
    float* attn = base + OFF_ATTN;
    float* x1   = base + OFF_X1;
    float* ff   = base + OFF_FF;

    cudaFuncSetAttribute(attn_kernel, cudaFuncAttributeMaxDynamicSharedMemorySize, AT_SMEM);

    // 1. h = LN1(x)
    ln_kernel<<<NTOK, 256>>>(x, ln1_w, ln1_b, h);
    // 2. qkv = h @ wqkv + bqkv
    sgemm_kernel<EPI_BIAS><<<dim3(DQKV / 128, NTOK / 128), 256>>>(
        h, wqkv, bqkv, nullptr, qkv, NTOK, DQKV, DMODEL);
    // 3. attention
    attn_kernel<<<dim3(SEQ / 64, NHEAD, 2), 256, AT_SMEM>>>(qkv, attn);
    // 4. x1 = x + attn @ wo + bo
    sgemm_kernel<EPI_BIAS_RES><<<dim3(DMODEL / 128, NTOK / 128), 256>>>(
        attn, wo, bo, x, x1, NTOK, DMODEL, DMODEL);
    // 5. h = LN2(x1)
    ln_kernel<<<NTOK, 256>>>(x1, ln2_w, ln2_b, h);
    // 6. ff = gelu(h @ w1 + b1)
    sgemm_kernel<EPI_BIAS_GELU><<<dim3(DFF / 128, NTOK / 128), 256>>>(
        h, w1, b1, nullptr, ff, NTOK, DFF, DMODEL);
    // 7. out = x1 + ff @ w2 + b2
    sgemm_kernel<EPI_BIAS_RES><<<dim3(DMODEL / 128, NTOK / 128), 256>>>(
        ff, w2, b2, x1, out, NTOK, DMODEL, DFF);
}

// round 7
// speedup vs baseline: 2.3933x; 2.3933x over previous
#include <cuda_runtime.h>
#include <cuda_bf16.h>
#include <stdint.h>
#include <math.h>

// ---------------------------------------------------------------------------
// NeuronBloomBlock: B=2, S=2048, D=2048, H=16, HD=128, FF=8192, fp32.
// R5: R3 tf32 tensor-core GEMM, fixed missing <stdint.h>.
// ---------------------------------------------------------------------------

#define NTOK   4096
#define DMODEL 2048
#define DQKV   6144
#define DFF    8192
#define SEQ    2048
#define NHEAD  16
#define HEADD  128
#define LNEPS  1e-5f

#define OFF_H    ((size_t)0)
#define OFF_QKV  ((size_t)8388608)
#define OFF_ATTN ((size_t)(8388608 + 25165824))
#define OFF_X1   ((size_t)(8388608 + 25165824 + 8388608))
#define OFF_FF   ((size_t)(8388608 + 25165824 + 8388608 + 8388608))
#define SCRATCH_FLOATS ((size_t)(8388608 + 25165824 + 8388608 + 8388608 + 33554432))

__device__ float g_scratch[SCRATCH_FLOATS];

// ---------------------------------------------------------------------------
// LayerNorm: one block per row (D=2048), 256 threads, 8 elems/thread.
// ---------------------------------------------------------------------------
__global__ void ln_kernel(const float* __restrict__ x, const float* __restrict__ w,
                          const float* __restrict__ bb, float* __restrict__ out) {
    __shared__ float red[8];
    __shared__ float stat[2];
    int row = blockIdx.x;
    int tid = threadIdx.x;
    const float* xr = x + (size_t)row * DMODEL;

    float4 a = *(const float4*)(xr + tid * 4);
    float4 b = *(const float4*)(xr + 1024 + tid * 4);

    float s = a.x + a.y + a.z + a.w + b.x + b.y + b.z + b.w;
    #pragma unroll
    for (int o = 16; o; o >>= 1) s += __shfl_xor_sync(0xffffffffu, s, o);
    if ((tid & 31) == 0) red[tid >> 5] = s;
    __syncthreads();
    if (tid < 8) {
        float t = red[tid];
        #pragma unroll
        for (int o = 4; o; o >>= 1) t += __shfl_xor_sync(0xffu, t, o);
        if (tid == 0) stat[0] = t;
    }
    __syncthreads();
    float mean = stat[0] * (1.0f / (float)DMODEL);

    float dx0 = a.x - mean, dx1 = a.y - mean, dx2 = a.z - mean, dx3 = a.w - mean;
    float dy0 = b.x - mean, dy1 = b.y - mean, dy2 = b.z - mean, dy3 = b.w - mean;
    float s2 = dx0*dx0 + dx1*dx1 + dx2*dx2 + dx3*dx3
             + dy0*dy0 + dy1*dy1 + dy2*dy2 + dy3*dy3;
    __syncthreads();
    #pragma unroll
    for (int o = 16; o; o >>= 1) s2 += __shfl_xor_sync(0xffffffffu, s2, o);
    if ((tid & 31) == 0) red[tid >> 5] = s2;
    __syncthreads();
    if (tid < 8) {
        float t = red[tid];
        #pragma unroll
        for (int o = 4; o; o >>= 1) t += __shfl_xor_sync(0xffu, t, o);
        if (tid == 0) stat[1] = t;
    }
    __syncthreads();
    float inv = rsqrtf(stat[1] * (1.0f / (float)DMODEL) + LNEPS);

    float4 w0 = *(const float4*)(w + tid * 4);
    float4 w1 = *(const float4*)(w + 1024 + tid * 4);
    float4 g0 = *(const float4*)(bb + tid * 4);
    float4 g1 = *(const float4*)(bb + 1024 + tid * 4);

    float* orow = out + (size_t)row * DMODEL;
    float4 r0, r1;
    r0.x = dx0 * inv * w0.x + g0.x; r0.y = dx1 * inv * w0.y + g0.y;
    r0.z = dx2 * inv * w0.z + g0.z; r0.w = dx3 * inv * w0.w + g0.w;
    r1.x = dy0 * inv * w1.x + g1.x; r1.y = dy1 * inv * w1.y + g1.y;
    r1.z = dy2 * inv * w1.z + g1.z; r1.w = dy3 * inv * w1.w + g1.w;
    *(float4*)(orow + tid * 4) = r0;
    *(float4*)(orow + 1024 + tid * 4) = r1;
}

// ---------------------------------------------------------------------------
// TF32 tensor-core GEMM: C[M,N] = A[M,K] @ W[K,N] + bias (+ residual | gelu)
// Block tile 128x128, K-tile 32, 128 threads = 4 warps (2x2), warp tile 64x64.
// mma.sync.aligned.m16n8k8.row.col.f32.tf32.tf32.f32
// ---------------------------------------------------------------------------
#define EPI_BIAS      0
#define EPI_BIAS_RES  1
#define EPI_BIAS_GELU 2

__device__ __forceinline__ float gelu_tanh(float v) {
    float t = tanhf(0.7978845608028654f * (v + 0.044715f * v * v * v));
    return 0.5f * v * (1.0f + t);
}

__device__ __forceinline__ unsigned int f2tf32(float x) {
    unsigned int y;
    asm("cvt.rna.tf32.f32 %0, %1;" : "=r"(y) : "f"(x));
    return y;
}

__device__ __forceinline__ void mma_tf32(float c[4],
        unsigned int a0, unsigned int a1, unsigned int a2, unsigned int a3,
        unsigned int b0, unsigned int b1) {
    asm volatile(
        "mma.sync.aligned.m16n8k8.row.col.f32.tf32.tf32.f32 "
        "{%0,%1,%2,%3}, {%4,%5,%6,%7}, {%8,%9}, {%0,%1,%2,%3};\n"
        : "+f"(c[0]), "+f"(c[1]), "+f"(c[2]), "+f"(c[3])
        : "r"(a0), "r"(a1), "r"(a2), "r"(a3), "r"(b0), "r"(b1));
}

template<int EPI>
__global__ __launch_bounds__(128, 2)
void tgemm_kernel(const float* __restrict__ A, const float* __restrict__ W,
                  const float* __restrict__ bias, const float* __restrict__ res,
                  float* __restrict__ C, int M, int N, int K) {
    __shared__ float As[128][36];   // [m][k], pad 36 -> frag loads conflict-free
    __shared__ float Bs[32][136];   // [k][n], pad 136 -> frag loads conflict-free

    int tid = threadIdx.x;
    int lane = tid & 31;
    int wid  = tid >> 5;
    int warp_m = wid >> 1;          // 0..1
    int warp_n = wid & 1;           // 0..1
    int bm = blockIdx.y * 128;
    int bn = blockIdx.x * 128;

    float c[4][8][4];
    #pragma unroll
    for (int mt = 0; mt < 4; ++mt)
        #pragma unroll
        for (int nt = 0; nt < 8; ++nt)
            #pragma unroll
            for (int r = 0; r < 4; ++r) c[mt][nt][r] = 0.0f;

    int lr  = lane >> 2;   // 0..7
    int lc  = lane & 3;    // 0..3

    for (int kt = 0; kt < K; kt += 32) {
        // ---- load A 128x32 and B 32x128 (tf32-rounded) ----
        #pragma unroll
        for (int u = 0; u < 8; ++u) {
            int idx = tid + u * 128;           // 0..1023
            int r  = idx >> 3;
            int k4 = (idx & 7) << 2;
            float4 v = *(const float4*)(A + (size_t)(bm + r) * K + kt + k4);
            float4 t;
            t.x = __uint_as_float(f2tf32(v.x));
            t.y = __uint_as_float(f2tf32(v.y));
            t.z = __uint_as_float(f2tf32(v.z));
            t.w = __uint_as_float(f2tf32(v.w));
            *(float4*)&As[r][k4] = t;

            int r2 = idx >> 5;
            int c4 = (idx & 31) << 2;
            float4 wv = *(const float4*)(W + (size_t)(kt + r2) * N + bn + c4);
            float4 t2;
            t2.x = __uint_as_float(f2tf32(wv.x));
            t2.y = __uint_as_float(f2tf32(wv.y));
            t2.z = __uint_as_float(f2tf32(wv.z));
            t2.w = __uint_as_float(f2tf32(wv.w));
            *(float4*)&Bs[r2][c4] = t2;
        }
        __syncthreads();

        #pragma unroll
        for (int ks = 0; ks < 4; ++ks) {
            unsigned int af[4][4];
            #pragma unroll
            for (int mt = 0; mt < 4; ++mt) {
                int row = warp_m * 64 + mt * 16 + lr;
                int col = ks * 8 + lc;
                af[mt][0] = __float_as_uint(As[row][col]);
                af[mt][1] = __float_as_uint(As[row + 8][col]);
                af[mt][2] = __float_as_uint(As[row][col + 4]);
                af[mt][3] = __float_as_uint(As[row + 8][col + 4]);
            }
            unsigned int bf[8][2];
            #pragma unroll
            for (int nt = 0; nt < 8; ++nt) {
                int ncol = warp_n * 64 + nt * 8 + lr;
                int krow = ks * 8 + lc;
                bf[nt][0] = __float_as_uint(Bs[krow][ncol]);
                bf[nt][1] = __float_as_uint(Bs[krow + 4][ncol]);
            }
            #pragma unroll
            for (int mt = 0; mt < 4; ++mt)
                #pragma unroll
                for (int nt = 0; nt < 8; ++nt)
                    mma_tf32(c[mt][nt], af[mt][0], af[mt][1], af[mt][2], af[mt][3],
                             bf[nt][0], bf[nt][1]);
        }
        __syncthreads();
    }

    // ---- epilogue ----
    #pragma unroll
    for (int mt = 0; mt < 4; ++mt) {
        int gr0 = bm + warp_m * 64 + mt * 16 + lr;
        int gr1 = gr0 + 8;
        #pragma unroll
        for (int nt = 0; nt < 8; ++nt) {
            int gc = bn + warp_n * 64 + nt * 8 + (lc << 1);
            float2 bv = *(const float2*)(bias + gc);
            float2 v0, v1;
            v0.x = c[mt][nt][0] + bv.x; v0.y = c[mt][nt][1] + bv.y;
            v1.x = c[mt][nt][2] + bv.x; v1.y = c[mt][nt][3] + bv.y;
            if (EPI == EPI_BIAS_RES) {
                float2 r0 = *(const float2*)(res + (size_t)gr0 * N + gc);
                float2 r1 = *(const float2*)(res + (size_t)gr1 * N + gc);
                v0.x += r0.x; v0.y += r0.y;
                v1.x += r1.x; v1.y += r1.y;
            }
            if (EPI == EPI_BIAS_GELU) {
                v0.x = gelu_tanh(v0.x); v0.y = gelu_tanh(v0.y);
                v1.x = gelu_tanh(v1.x); v1.y = gelu_tanh(v1.y);
            }
            *(float2*)(C + (size_t)gr0 * N + gc) = v0;
            *(float2*)(C + (size_t)gr1 * N + gc) = v1;
        }
    }
}

// ---------------------------------------------------------------------------
// Flash attention (fp32) with ALiBi + causal mask. (unchanged from R2)
// ---------------------------------------------------------------------------
#define AT_SMEM ((3 * 64 * 132 + 64 * 68) * 4)

__global__ __launch_bounds__(256)
void attn_kernel(const float* __restrict__ qkv, float* __restrict__ out) {
    extern __shared__ float sm[];
    float* Qs = sm;                  // [64][132]
    float* Ks = sm + 64 * 132;       // [64][132]
    float* Vs = sm + 2 * 64 * 132;   // [64][132]
    float* Ps = sm + 3 * 64 * 132;   // [64][68]

    int tid = threadIdx.x;
    int tx = tid & 15, ty = tid >> 4;
    int qt = blockIdx.x, h = blockIdx.y, b = blockIdx.z;
    int q0 = qt * 64;

    const float scale = 0.08838834764831845f;   // 1/sqrt(128)
    float slope = exp2f(-0.5f * (float)(h + 1));

    const float* qbase = qkv + (size_t)b * SEQ * DQKV + (size_t)h * HEADD;
    const float* kbase = qbase + DMODEL;
    const float* vbase = qbase + 2 * DMODEL;

    for (int i = tid; i < 64 * 32; i += 256) {
        int r = i >> 5, c4 = (i & 31) << 2;
        float4 v = *(const float4*)(qbase + (size_t)(q0 + r) * DQKV + c4);
        Qs[r * 132 + c4 + 0] = v.x * scale;
        Qs[r * 132 + c4 + 1] = v.y * scale;
        Qs[r * 132 + c4 + 2] = v.z * scale;
        Qs[r * 132 + c4 + 3] = v.w * scale;
    }

    float m_i[4], l_i[4], acc[4][8];
    #pragma unroll
    for (int i = 0; i < 4; ++i) {
        m_i[i] = -INFINITY; l_i[i] = 0.0f;
        #pragma unroll
        for (int c = 0; c < 8; ++c) acc[i][c] = 0.0f;
    }

    int nkb = qt + 1;
    for (int kb = 0; kb < nkb; ++kb) {
        __syncthreads();
        for (int i = tid; i < 64 * 32; i += 256) {
            int r = i >> 5, c4 = (i & 31) << 2;
            *(float4*)&Ks[r * 132 + c4] =
                *(const float4*)(kbase + (size_t)(kb * 64 + r) * DQKV + c4);
            *(float4*)&Vs[r * 132 + c4] =
                *(const float4*)(vbase + (size_t)(kb * 64 + r) * DQKV + c4);
        }
        __syncthreads();

        float s[4][4];
        #pragma unroll
        for (int i = 0; i < 4; ++i)
            #pragma unroll
            for (int j = 0; j < 4; ++j) s[i][j] = 0.0f;

        for (int d4 = 0; d4 < 32; ++d4) {
            float4 qv[4], kv[4];
            #pragma unroll
            for (int i = 0; i < 4; ++i)
                qv[i] = *(const float4*)&Qs[(ty * 4 + i) * 132 + d4 * 4];
            #pragma unroll
            for (int j = 0; j < 4; ++j)
                kv[j] = *(const float4*)&Ks[(j * 16 + tx) * 132 + d4 * 4];
            #pragma unroll
            for (int i = 0; i < 4; ++i)
                #pragma unroll
                for (int j = 0; j < 4; ++j) {
                    s[i][j] = fmaf(qv[i].x, kv[j].x, s[i][j]);
                    s[i][j] = fmaf(qv[i].y, kv[j].y, s[i][j]);
                    s[i][j] = fmaf(qv[i].z, kv[j].z, s[i][j]);
                    s[i][j] = fmaf(qv[i].w, kv[j].w, s[i][j]);
                }
        }

        bool diag = (kb == qt);
        float a4[4];
        #pragma unroll
        for (int i = 0; i < 4; ++i) {
            int gr = q0 + ty * 4 + i;
            float rowmax = -1e30f;
            #pragma unroll
            for (int j = 0; j < 4; ++j) {
                int gc = kb * 64 + j * 16 + tx;
                float val = s[i][j] + slope * (float)(gc - gr);
                if (diag && gc > gr) val = -1e30f;
                s[i][j] = val;
                rowmax = fmaxf(rowmax, val);
            }
            #pragma unroll
            for (int o = 8; o; o >>= 1)
                rowmax = fmaxf(rowmax, __shfl_xor_sync(0xffffffffu, rowmax, o, 16));
            float mnew = fmaxf(m_i[i], rowmax);
            float alpha = expf(m_i[i] - mnew);
            float rowsum = 0.0f;
            #pragma unroll
            for (int j = 0; j < 4; ++j) {
                float p = expf(s[i][j] - mnew);
                s[i][j] = p;
                rowsum += p;
            }
            #pragma unroll
            for (int o = 8; o; o >>= 1)
                rowsum += __shfl_xor_sync(0xffffffffu, rowsum, o, 16);
            l_i[i] = l_i[i] * alpha + rowsum;
            m_i[i] = mnew;
            a4[i] = alpha;
        }

        #pragma unroll
        for (int i = 0; i < 4; ++i)
            #pragma unroll
            for (int j = 0; j < 4; ++j)
                Ps[(ty * 4 + i) * 68 + j * 16 + tx] = s[i][j];
        __syncthreads();

        #pragma unroll
        for (int i = 0; i < 4; ++i)
            #pragma unroll
            for (int c = 0; c < 8; ++c) acc[i][c] *= a4[i];

        #pragma unroll 4
        for (int k = 0; k < 64; ++k) {
            float4 v0 = *(const float4*)&Vs[k * 132 + tx * 4];
            float4 v1 = *(const float4*)&Vs[k * 132 + 64 + tx * 4];
            #pragma unroll
            for (int i = 0; i < 4; ++i) {
                float p = Ps[(ty * 4 + i) * 68 + k];
                acc[i][0] = fmaf(p, v0.x, acc[i][0]);
                acc[i][1] = fmaf(p, v0.y, acc[i][1]);
                acc[i][2] = fmaf(p, v0.z, acc[i][2]);
                acc[i][3] = fmaf(p, v0.w, acc[i][3]);
                acc[i][4] = fmaf(p, v1.x, acc[i][4]);
                acc[i][5] = fmaf(p, v1.y, acc[i][5]);
                acc[i][6] = fmaf(p, v1.z, acc[i][6]);
                acc[i][7] = fmaf(p, v1.w, acc[i][7]);
            }
        }
    }

    #pragma unroll
    for (int i = 0; i < 4; ++i) {
        float inv = 1.0f / l_i[i];
        size_t orow = ((size_t)(b * SEQ + q0 + ty * 4 + i)) * DMODEL + h * HEADD;
        float4 o0, o1;
        o0.x = acc[i][0] * inv; o0.y = acc[i][1] * inv;
        o0.z = acc[i][2] * inv; o0.w = acc[i][3] * inv;
        o1.x = acc[i][4] * inv; o1.y = acc[i][5] * inv;
        o1.z = acc[i][6] * inv; o1.w = acc[i][7] * inv;
        *(float4*)(out + orow + tx * 4) = o0;
        *(float4*)(out + orow + 64 + tx * 4) = o1;
    }
}

// ---------------------------------------------------------------------------
extern "C" void kernel_launch(void* const* d_in, const int* in_sizes, int n_in,
                              void* d_out, int out_size) {
    const float* x     = (const float*)d_in[0];
    const float* ln1_w = (const float*)d_in[1];
    const float* ln1_b = (const float*)d_in[2];
    const float* wqkv  = (const float*)d_in[3];
    const float* bqkv  = (const float*)d_in[4];
    const float* wo    = (const float*)d_in[5];
    const float* bo    = (const float*)d_in[6];
    const float* ln2_w = (const float*)d_in[7];
    const float* ln2_b = (const float*)d_in[8];
    const float* w1    = (const float*)d_in[9];
    const float* b1    = (const float*)d_in[10];
    const float* w2    = (const float*)d_in[11];
    const float* b2    = (const float*)d_in[12];
    float* out = (float*)d_out;

    float* base = nullptr;
    cudaGetSymbolAddress((void**)&base, g_scratch);
    float* h    = base + OFF_H;
    float* qkv  = base + OFF_QKV;
    float* attn = base + OFF_ATTN;
    float* x1   = base + OFF_X1;
    float* ff   = base + OFF_FF;

    cudaFuncSetAttribute(attn_kernel, cudaFuncAttributeMaxDynamicSharedMemorySize, AT_SMEM);

    // 1. h = LN1(x)
    ln_kernel<<<NTOK, 256>>>(x, ln1_w, ln1_b, h);
    // 2. qkv = h @ wqkv + bqkv
    tgemm_kernel<EPI_BIAS><<<dim3(DQKV / 128, NTOK / 128), 128>>>(
        h, wqkv, bqkv, nullptr, qkv, NTOK, DQKV, DMODEL);
    // 3. attention
    attn_kernel<<<dim3(SEQ / 64, NHEAD, 2), 256, AT_SMEM>>>(qkv, attn);
    // 4. x1 = x + attn @ wo + bo
    tgemm_kernel<EPI_BIAS_RES><<<dim3(DMODEL / 128, NTOK / 128), 128>>>(
        attn, wo, bo, x, x1, NTOK, DMODEL, DMODEL);
    // 5. h = LN2(x1)
    ln_kernel<<<NTOK, 256>>>(x1, ln2_w, ln2_b, h);
    // 6. ff = gelu(h @ w1 + b1)
    tgemm_kernel<EPI_BIAS_GELU><<<dim3(DFF / 128, NTOK / 128), 128>>>(
        h, w1, b1, nullptr, ff, NTOK, DFF, DMODEL);
    // 7. out = x1 + ff @ w2 + b2
    tgemm_kernel<EPI_BIAS_RES><<<dim3(DMODEL / 128, NTOK / 128), 128>>>(
        ff, w2, b2, x1, out, NTOK, DMODEL, DFF);
}